// round 10
// baseline (speedup 1.0000x reference)
#include <cuda_runtime.h>
#include <cuda_bf16.h>
#include <cuda_fp16.h>
#include <cstdint>
#include <math.h>

// N=50000, H=256, E=300000.
// g = MLP(emb) once over nodes (exact restructure), per-edge cosine gather.
// GEMMs: warp-level HMMA (mma.sync bf16; tcgen05 unavailable on this
// harness's compute_103 target). Split precision 3-product.
// This round: gemm2 writes g directly as fp16 (+fp32 row sumsq parts);
// the separate normalize pass is deleted; edge kernel divides by exact norms.

#define H256 256
#define NPAD 50176  // 784*64

// ---------------- device scratch (allocation-free) ----------------
__device__ __align__(16) __half         g_g16[(size_t)NPAD * H256];   // g as fp16
__device__ __align__(16) __nv_bfloat16  g_h_hi[(size_t)NPAD * H256];
__device__ __align__(16) __nv_bfloat16  g_h_lo[(size_t)NPAD * H256];
__device__ __align__(16) __nv_bfloat16  g_w1_hi[H256 * H256];
__device__ __align__(16) __nv_bfloat16  g_w1_lo[H256 * H256];
__device__ __align__(16) __nv_bfloat16  g_w2_hi[H256 * H256];
__device__ __align__(16) __nv_bfloat16  g_w2_lo[H256 * H256];
__device__ float g_sumsq[2 * NPAD];     // per-column-tile partial row sumsq

// ---------------- PTX helpers ----------------
__device__ __forceinline__ uint32_t smem_u32(const void* p) {
    uint32_t a;
    asm("{ .reg .u64 t; cvta.to.shared.u64 t, %1; cvt.u32.u64 %0, t; }" : "=r"(a) : "l"(p));
    return a;
}
__device__ __forceinline__ void cp16(uint32_t s, const void* g) {
    asm volatile("cp.async.cg.shared.global [%0], [%1], 16;"
                 :: "r"(s), "l"(__cvta_generic_to_global(g)) : "memory");
}
__device__ __forceinline__ void cp_commit() {
    asm volatile("cp.async.commit_group;" ::: "memory");
}
template <int NN>
__device__ __forceinline__ void cp_wait() {
    asm volatile("cp.async.wait_group %0;" :: "n"(NN) : "memory");
}
__device__ __forceinline__ void ldsm4(uint32_t* r, uint32_t addr) {
    asm volatile("ldmatrix.sync.aligned.m8n8.x4.shared.b16 {%0,%1,%2,%3}, [%4];"
                 : "=r"(r[0]), "=r"(r[1]), "=r"(r[2]), "=r"(r[3]) : "r"(addr));
}
__device__ __forceinline__ void mma_bf16(float* c, const uint32_t* a, const uint32_t* b) {
    asm volatile(
        "mma.sync.aligned.m16n8k16.row.col.f32.bf16.bf16.f32 "
        "{%0,%1,%2,%3}, {%4,%5,%6,%7}, {%8,%9}, {%0,%1,%2,%3};"
        : "+f"(c[0]), "+f"(c[1]), "+f"(c[2]), "+f"(c[3])
        : "r"(a[0]), "r"(a[1]), "r"(a[2]), "r"(a[3]), "r"(b[0]), "r"(b[1]));
}
__device__ __forceinline__ uint32_t pack_bf2(float a, float b) {
    __nv_bfloat162 t = __floats2bfloat162_rn(a, b);
    return *reinterpret_cast<uint32_t*>(&t);
}
__device__ __forceinline__ uint32_t pack_h2(float a, float b) {
    __half2 t = __floats2half2_rn(a, b);
    return *reinterpret_cast<uint32_t*>(&t);
}

// SMEM (per-CTA 96KB):
//  A stage st: base st*16384; hi +0 (8KB: 64r x 64k bf16), lo +8192
//  B stage st: base 32768 + st*32768; hi +0 (16KB: 128r x 64k), lo +16384
#define A_ST(st)  ((uint32_t)(st) * 16384u)
#define B_ST(st)  (32768u + (uint32_t)(st) * 32768u)
#define SMEM_BYTES 98304

// ---------------------------------------------------------------------------
// HMMA split-bf16 GEMM: C[64,128] tile/CTA, 256 thr (8 warps, 2m x 4n, 32x32).
// K=256 in 4 chunks of 64; A and B chunk-double-buffered. 2 CTAs/SM.
// mode 0: A = fp32 (split on the fly, reg-staged); out = relu(C+bias) split.
// mode 1: A = bf16 hi/lo (cp.async); out = fp16 C+bias + fp32 row sumsq part.
// ---------------------------------------------------------------------------
__global__ __launch_bounds__(256, 2) void gemm_hmma(
    const float* __restrict__ A32,
    const __nv_bfloat16* __restrict__ Ahi, const __nv_bfloat16* __restrict__ Alo,
    const __nv_bfloat16* __restrict__ Bhi, const __nv_bfloat16* __restrict__ Blo,
    const float* __restrict__ bias, int Nn, int mode,
    __nv_bfloat16* __restrict__ OutHi, __nv_bfloat16* __restrict__ OutLo,
    __half* __restrict__ OutH, float* __restrict__ sumsq)
{
    extern __shared__ char smem[];
    const uint32_t sb = smem_u32(smem);
    const int tid  = threadIdx.x;
    const int lane = tid & 31, wid = tid >> 5;
    const int wm = wid & 1, wn = wid >> 1;        // 2 x 4 warp grid (32x32 tiles)
    const int row0 = blockIdx.x * 64;
    const int col0 = blockIdx.y * 128;

    float C[2][4][4];
#pragma unroll
    for (int i = 0; i < 2; i++)
#pragma unroll
        for (int j = 0; j < 4; j++)
#pragma unroll
            for (int q = 0; q < 4; q++) C[i][j][q] = 0.0f;

    // ---- ldmatrix lane addressing ----
    const int a_r  = wm * 32 + (lane & 7) + ((lane >> 3) & 1) * 8;
    const int a_kq = ((lane >> 4) & 1) * 8;
    const int b_n  = wn * 32 + (lane & 7) + ((lane >> 4) & 1) * 8;
    const int b_kq = ((lane >> 3) & 1) * 8;
    uint32_t aRow[2], aMask[2], bRow[2], bMask[2];
#pragma unroll
    for (int i = 0; i < 2; i++) {
        int r = a_r + i * 16;
        aRow[i]  = (uint32_t)(r * 128);
        aMask[i] = (uint32_t)((r & 7) << 4);
    }
#pragma unroll
    for (int j = 0; j < 2; j++) {
        int n = b_n + j * 16;
        bRow[j]  = (uint32_t)(n * 128);
        bMask[j] = (uint32_t)((n & 7) << 4);
    }

    // ---- loader helpers ----
    auto loadB = [&](int kc, int st) {
        uint32_t bh = sb + B_ST(st), bl = bh + 16384u;
#pragma unroll
        for (int it = 0; it < 4; it++) {
            int idx = tid + it * 256;          // 0..1023
            int r = idx >> 3, c8 = idx & 7;
            uint32_t off = (uint32_t)(r * 128 + ((c8 * 16) ^ ((r & 7) << 4)));
            size_t gofs = (size_t)(col0 + r) * H256 + kc * 64 + c8 * 8;
            cp16(bh + off, Bhi + gofs);
            cp16(bl + off, Blo + gofs);
        }
    };
    auto loadA1 = [&](int kc, int st) {        // mode 1: bf16 split via cp.async
        uint32_t ah = sb + A_ST(st), al = ah + 8192u;
#pragma unroll
        for (int it = 0; it < 2; it++) {
            int idx = tid + it * 256;          // 0..511
            int r = idx >> 3, c8 = idx & 7;
            uint32_t off = (uint32_t)(r * 128 + ((c8 * 16) ^ ((r & 7) << 4)));
            size_t gofs = (size_t)(row0 + r) * H256 + kc * 64 + c8 * 8;
            cp16(ah + off, Ahi + gofs);
            cp16(al + off, Alo + gofs);
        }
    };

    float4 regs[4];
    auto fetchA0 = [&](int kc) {               // mode 0: fp32 -> regs (guarded)
#pragma unroll
        for (int it = 0; it < 4; it++) {
            int idx = tid + it * 256;          // 0..1023 float4 units
            int r = idx >> 4, k4u = idx & 15;
            regs[it] = (row0 + r < Nn)
                ? *(const float4*)(A32 + (size_t)(row0 + r) * H256 + kc * 64 + k4u * 4)
                : make_float4(0.f, 0.f, 0.f, 0.f);
        }
    };
    auto storeA0 = [&](int st) {               // regs -> split bf16 smem
        const uint32_t base = A_ST(st);
#pragma unroll
        for (int it = 0; it < 4; it++) {
            int idx = tid + it * 256;
            int r = idx >> 4, k4u = idx & 15;
            float4 v = regs[it];
            float h0 = __bfloat162float(__float2bfloat16_rn(v.x));
            float h1 = __bfloat162float(__float2bfloat16_rn(v.y));
            float h2 = __bfloat162float(__float2bfloat16_rn(v.z));
            float h3 = __bfloat162float(__float2bfloat16_rn(v.w));
            uint32_t off = (uint32_t)(r * 128 + ((k4u * 8) ^ ((r & 7) << 4)));
            *(uint2*)(smem + base + off) = make_uint2(pack_bf2(h0, h1), pack_bf2(h2, h3));
            *(uint2*)(smem + base + 8192 + off) =
                make_uint2(pack_bf2(v.x - h0, v.y - h1), pack_bf2(v.z - h2, v.w - h3));
        }
    };

    // ---- prologue: chunk 0 in flight ----
    loadB(0, 0);
    if (mode == 1) loadA1(0, 0);
    cp_commit();
    if (mode == 0) fetchA0(0);

#pragma unroll
    for (int kc = 0; kc < 4; kc++) {
        const int st = kc & 1;
        if (mode == 0) storeA0(st);            // safe: stage st idle since sync(kc-1)
        cp_wait<0>();                          // chunk kc async loads arrived
        __syncthreads();                       // all warps done MMA(kc-1)
        if (kc < 3) {                          // next chunk into the other stage
            loadB(kc + 1, st ^ 1);
            if (mode == 1) loadA1(kc + 1, st ^ 1);
            cp_commit();
            if (mode == 0) fetchA0(kc + 1);    // global->regs overlaps MMA
        }

        const uint32_t aH = sb + A_ST(st), aL = aH + 8192u;
        const uint32_t bH = sb + B_ST(st), bL = bH + 16384u;
#pragma unroll
        for (int s = 0; s < 4; s++) {
            const int k0 = s * 16;
            uint32_t ah[2][4], al[2][4], bh[2][4], bl[2][4];
#pragma unroll
            for (int i = 0; i < 2; i++) {
                uint32_t off = aRow[i] + (((uint32_t)((k0 + a_kq) * 2)) ^ aMask[i]);
                ldsm4(ah[i], aH + off);
                ldsm4(al[i], aL + off);
            }
#pragma unroll
            for (int j = 0; j < 2; j++) {
                uint32_t off = bRow[j] + (((uint32_t)((k0 + b_kq) * 2)) ^ bMask[j]);
                ldsm4(bh[j], bH + off);
                ldsm4(bl[j], bL + off);
            }
#pragma unroll
            for (int i = 0; i < 2; i++)
#pragma unroll
                for (int j = 0; j < 2; j++)
#pragma unroll
                    for (int h = 0; h < 2; h++) {
                        const int ns = j * 2 + h;
                        mma_bf16(C[i][ns], ah[i], &bh[j][2 * h]);
                        mma_bf16(C[i][ns], ah[i], &bl[j][2 * h]);
                        mma_bf16(C[i][ns], al[i], &bh[j][2 * h]);
                    }
        }
    }

    // ---- Epilogue ----
    const int rbase = row0 + wm * 32 + (lane >> 2);
    const int cbase = col0 + wn * 32 + (lane & 3) * 2;
    float ss[2][2] = {{0.f, 0.f}, {0.f, 0.f}};

#pragma unroll
    for (int i = 0; i < 2; i++) {
#pragma unroll
        for (int ns = 0; ns < 4; ns++) {
            const int c   = cbase + ns * 8;
            const float bv0 = __ldg(&bias[c]);
            const float bv1 = __ldg(&bias[c + 1]);
#pragma unroll
            for (int rh = 0; rh < 2; rh++) {
                const int r = rbase + i * 16 + rh * 8;
                float v0 = C[i][ns][rh * 2 + 0] + bv0;
                float v1 = C[i][ns][rh * 2 + 1] + bv1;
                const size_t go = (size_t)r * H256 + c;
                if (mode == 0) {
                    v0 = fmaxf(v0, 0.0f);
                    v1 = fmaxf(v1, 0.0f);
                    float h0 = __bfloat162float(__float2bfloat16_rn(v0));
                    float h1 = __bfloat162float(__float2bfloat16_rn(v1));
                    *(uint32_t*)(OutHi + go) = pack_bf2(h0, h1);
                    *(uint32_t*)(OutLo + go) = pack_bf2(v0 - h0, v1 - h1);
                } else {
                    *(uint32_t*)(OutH + go) = pack_h2(v0, v1);
                    ss[i][rh] = fmaf(v0, v0, ss[i][rh]);
                    ss[i][rh] = fmaf(v1, v1, ss[i][rh]);
                }
            }
        }
    }

    if (mode == 1) {
        // Deterministic in-CTA row reduction; plain store to this column
        // tile's partial array (no atomics needed).
        __syncthreads();                       // MMA readers done; reuse smem
        float* red = (float*)smem;             // 64 rows x 4 (wn)
#pragma unroll
        for (int i = 0; i < 2; i++)
#pragma unroll
            for (int rh = 0; rh < 2; rh++) {
                float s = ss[i][rh];
                s += __shfl_xor_sync(0xffffffffu, s, 1);
                s += __shfl_xor_sync(0xffffffffu, s, 2);
                int rl = wm * 32 + (lane >> 2) + i * 16 + rh * 8;
                if ((lane & 3) == 0) red[rl * 4 + wn] = s;
            }
        __syncthreads();
        if (tid < 64) {
            float s = ((red[tid * 4] + red[tid * 4 + 1]) + red[tid * 4 + 2]) + red[tid * 4 + 3];
            sumsq[(size_t)blockIdx.y * NPAD + row0 + tid] = s;
        }
    }
}

// ---------------------------------------------------------------------------
// Prep: split W1/W2 into bf16 hi/lo.
// ---------------------------------------------------------------------------
__global__ __launch_bounds__(256) void prep_w(
    const float* __restrict__ W1, const float* __restrict__ W2,
    __nv_bfloat16* w1h, __nv_bfloat16* w1l,
    __nv_bfloat16* w2h, __nv_bfloat16* w2l)
{
    int i = blockIdx.x * 256 + threadIdx.x;
    if (i < H256 * H256) {
        float a = W1[i];
        __nv_bfloat16 h = __float2bfloat16_rn(a);
        w1h[i] = h;
        w1l[i] = __float2bfloat16_rn(a - __bfloat162float(h));
        float b = W2[i];
        __nv_bfloat16 h2 = __float2bfloat16_rn(b);
        w2h[i] = h2;
        w2l[i] = __float2bfloat16_rn(b - __bfloat162float(h2));
    }
}

// ---------------------------------------------------------------------------
// Edge kernel: one warp per edge; fp16 g rows (25 MB, L2-resident).
// out[e] = dot(g16[col], g16[row]) / (||g[col]|| * ||g[row]||), norms from
// exact fp32 sumsq partials (two per row, combined here).
// ---------------------------------------------------------------------------
__global__ __launch_bounds__(256) void edge_kernel(
    const __half* __restrict__ g16, const float* __restrict__ ssq,
    const int* __restrict__ ei, float* __restrict__ out, int E, int N)
{
    int e    = blockIdx.x * 8 + (threadIdx.x >> 5);
    int lane = threadIdx.x & 31;
    if (e >= E) return;
    int c = ei[e];
    int r = ei[E + e];
    c = min(max(c, 0), N - 1);
    r = min(max(r, 0), N - 1);
    uint4 a = *(const uint4*)(g16 + (size_t)c * H256 + lane * 8);
    uint4 b = *(const uint4*)(g16 + (size_t)r * H256 + lane * 8);
    const __half2* ha = (const __half2*)&a;
    const __half2* hb = (const __half2*)&b;
    float s = 0.0f;
#pragma unroll
    for (int i = 0; i < 4; i++) {
        float2 fa = __half22float2(ha[i]);
        float2 fb = __half22float2(hb[i]);
        s = fmaf(fa.x, fb.x, s);
        s = fmaf(fa.y, fb.y, s);
    }
#pragma unroll
    for (int o = 16; o; o >>= 1) s += __shfl_xor_sync(0xffffffffu, s, o);
    if (lane == 0) {
        float nc = fmaxf(sqrtf(ssq[c] + ssq[NPAD + c]), 1e-8f);
        float nr = fmaxf(sqrtf(ssq[r] + ssq[NPAD + r]), 1e-8f);
        out[e] = s / (nc * nr);
    }
}

// ---------------------------------------------------------------------------
extern "C" void kernel_launch(void* const* d_in, const int* in_sizes, int n_in,
                              void* d_out, int out_size)
{
    const float* emb = (const float*)d_in[0];
    const int*   ei  = (const int*)d_in[1];
    const float* W1  = (const float*)d_in[2];
    const float* b1  = (const float*)d_in[3];
    const float* W2  = (const float*)d_in[4];
    const float* b2  = (const float*)d_in[5];
    float*       out = (float*)d_out;

    const int Hn = in_sizes[3];
    const int N  = in_sizes[0] / Hn;
    const int E  = in_sizes[1] / 2;
    if (Hn != H256 || N > NPAD) return;

    float* ssbuf;
    __half* g16;
    __nv_bfloat16 *hhi, *hlo, *w1h, *w1l, *w2h, *w2l;
    cudaGetSymbolAddress((void**)&g16,   g_g16);
    cudaGetSymbolAddress((void**)&hhi,   g_h_hi);
    cudaGetSymbolAddress((void**)&hlo,   g_h_lo);
    cudaGetSymbolAddress((void**)&w1h,   g_w1_hi);
    cudaGetSymbolAddress((void**)&w1l,   g_w1_lo);
    cudaGetSymbolAddress((void**)&w2h,   g_w2_hi);
    cudaGetSymbolAddress((void**)&w2l,   g_w2_lo);
    cudaGetSymbolAddress((void**)&ssbuf, g_sumsq);

    cudaFuncSetAttribute(gemm_hmma, cudaFuncAttributeMaxDynamicSharedMemorySize, SMEM_BYTES);

    prep_w<<<(H256 * H256 + 255) / 256, 256>>>(W1, W2, w1h, w1l, w2h, w2l);

    dim3 ggrid(NPAD / 64, 2);
    // Layer 1: h = relu(emb @ W1^T + b1), emb split on the fly, h stored split
    gemm_hmma<<<ggrid, 256, SMEM_BYTES>>>(emb, nullptr, nullptr, w1h, w1l, b1, N, 0,
                                          hhi, hlo, nullptr, nullptr);
    // Layer 2: g = h @ W2^T + b2 -> fp16 table + fp32 row sumsq parts
    gemm_hmma<<<ggrid, 256, SMEM_BYTES>>>(nullptr, hhi, hlo, w2h, w2l, b2, N, 1,
                                          nullptr, nullptr, g16, ssbuf);
    // Per-edge cosine
    edge_kernel<<<(E + 7) / 8, 256>>>(g16, ssbuf, ei, out, E, N);
}

// round 11
// speedup vs baseline: 1.2121x; 1.2121x over previous
#include <cuda_runtime.h>
#include <cuda_bf16.h>
#include <cuda_fp16.h>
#include <cstdint>
#include <math.h>

// N=50000, H=256, E=300000.
// g = MLP(emb) once over nodes (exact restructure), per-edge cosine gather.
// GEMMs: warp-level HMMA (mma.sync bf16; tcgen05 unavailable on this
// harness's compute_103 target). Split precision 3-product.
// This round: edge kernel restructured to 8 lanes/edge, 4 edges/warp,
// hfma2 inner product, early norm prefetch — attacks the issue-bound profile.

#define H256 256
#define NPAD 50176  // 784*64

// ---------------- device scratch (allocation-free) ----------------
__device__ __align__(16) __half         g_g16[(size_t)NPAD * H256];   // g as fp16
__device__ __align__(16) __nv_bfloat16  g_h_hi[(size_t)NPAD * H256];
__device__ __align__(16) __nv_bfloat16  g_h_lo[(size_t)NPAD * H256];
__device__ __align__(16) __nv_bfloat16  g_w1_hi[H256 * H256];
__device__ __align__(16) __nv_bfloat16  g_w1_lo[H256 * H256];
__device__ __align__(16) __nv_bfloat16  g_w2_hi[H256 * H256];
__device__ __align__(16) __nv_bfloat16  g_w2_lo[H256 * H256];
__device__ float g_sumsq[2 * NPAD];     // per-column-tile partial row sumsq

// ---------------- PTX helpers ----------------
__device__ __forceinline__ uint32_t smem_u32(const void* p) {
    uint32_t a;
    asm("{ .reg .u64 t; cvta.to.shared.u64 t, %1; cvt.u32.u64 %0, t; }" : "=r"(a) : "l"(p));
    return a;
}
__device__ __forceinline__ void cp16(uint32_t s, const void* g) {
    asm volatile("cp.async.cg.shared.global [%0], [%1], 16;"
                 :: "r"(s), "l"(__cvta_generic_to_global(g)) : "memory");
}
__device__ __forceinline__ void cp_commit() {
    asm volatile("cp.async.commit_group;" ::: "memory");
}
template <int NN>
__device__ __forceinline__ void cp_wait() {
    asm volatile("cp.async.wait_group %0;" :: "n"(NN) : "memory");
}
__device__ __forceinline__ void ldsm4(uint32_t* r, uint32_t addr) {
    asm volatile("ldmatrix.sync.aligned.m8n8.x4.shared.b16 {%0,%1,%2,%3}, [%4];"
                 : "=r"(r[0]), "=r"(r[1]), "=r"(r[2]), "=r"(r[3]) : "r"(addr));
}
__device__ __forceinline__ void mma_bf16(float* c, const uint32_t* a, const uint32_t* b) {
    asm volatile(
        "mma.sync.aligned.m16n8k16.row.col.f32.bf16.bf16.f32 "
        "{%0,%1,%2,%3}, {%4,%5,%6,%7}, {%8,%9}, {%0,%1,%2,%3};"
        : "+f"(c[0]), "+f"(c[1]), "+f"(c[2]), "+f"(c[3])
        : "r"(a[0]), "r"(a[1]), "r"(a[2]), "r"(a[3]), "r"(b[0]), "r"(b[1]));
}
__device__ __forceinline__ uint32_t pack_bf2(float a, float b) {
    __nv_bfloat162 t = __floats2bfloat162_rn(a, b);
    return *reinterpret_cast<uint32_t*>(&t);
}
__device__ __forceinline__ uint32_t pack_h2(float a, float b) {
    __half2 t = __floats2half2_rn(a, b);
    return *reinterpret_cast<uint32_t*>(&t);
}

// SMEM (per-CTA 96KB):
//  A stage st: base st*16384; hi +0 (8KB: 64r x 64k bf16), lo +8192
//  B stage st: base 32768 + st*32768; hi +0 (16KB: 128r x 64k), lo +16384
#define A_ST(st)  ((uint32_t)(st) * 16384u)
#define B_ST(st)  (32768u + (uint32_t)(st) * 32768u)
#define SMEM_BYTES 98304

// ---------------------------------------------------------------------------
// HMMA split-bf16 GEMM: C[64,128] tile/CTA, 256 thr (8 warps, 2m x 4n, 32x32).
// K=256 in 4 chunks of 64; A and B chunk-double-buffered. 2 CTAs/SM.
// mode 0: A = fp32 (split on the fly, reg-staged); out = relu(C+bias) split.
// mode 1: A = bf16 hi/lo (cp.async); out = fp16 C+bias + fp32 row sumsq part.
// ---------------------------------------------------------------------------
__global__ __launch_bounds__(256, 2) void gemm_hmma(
    const float* __restrict__ A32,
    const __nv_bfloat16* __restrict__ Ahi, const __nv_bfloat16* __restrict__ Alo,
    const __nv_bfloat16* __restrict__ Bhi, const __nv_bfloat16* __restrict__ Blo,
    const float* __restrict__ bias, int Nn, int mode,
    __nv_bfloat16* __restrict__ OutHi, __nv_bfloat16* __restrict__ OutLo,
    __half* __restrict__ OutH, float* __restrict__ sumsq)
{
    extern __shared__ char smem[];
    const uint32_t sb = smem_u32(smem);
    const int tid  = threadIdx.x;
    const int lane = tid & 31, wid = tid >> 5;
    const int wm = wid & 1, wn = wid >> 1;        // 2 x 4 warp grid (32x32 tiles)
    const int row0 = blockIdx.x * 64;
    const int col0 = blockIdx.y * 128;

    float C[2][4][4];
#pragma unroll
    for (int i = 0; i < 2; i++)
#pragma unroll
        for (int j = 0; j < 4; j++)
#pragma unroll
            for (int q = 0; q < 4; q++) C[i][j][q] = 0.0f;

    // ---- ldmatrix lane addressing ----
    const int a_r  = wm * 32 + (lane & 7) + ((lane >> 3) & 1) * 8;
    const int a_kq = ((lane >> 4) & 1) * 8;
    const int b_n  = wn * 32 + (lane & 7) + ((lane >> 4) & 1) * 8;
    const int b_kq = ((lane >> 3) & 1) * 8;
    uint32_t aRow[2], aMask[2], bRow[2], bMask[2];
#pragma unroll
    for (int i = 0; i < 2; i++) {
        int r = a_r + i * 16;
        aRow[i]  = (uint32_t)(r * 128);
        aMask[i] = (uint32_t)((r & 7) << 4);
    }
#pragma unroll
    for (int j = 0; j < 2; j++) {
        int n = b_n + j * 16;
        bRow[j]  = (uint32_t)(n * 128);
        bMask[j] = (uint32_t)((n & 7) << 4);
    }

    // ---- loader helpers ----
    auto loadB = [&](int kc, int st) {
        uint32_t bh = sb + B_ST(st), bl = bh + 16384u;
#pragma unroll
        for (int it = 0; it < 4; it++) {
            int idx = tid + it * 256;          // 0..1023
            int r = idx >> 3, c8 = idx & 7;
            uint32_t off = (uint32_t)(r * 128 + ((c8 * 16) ^ ((r & 7) << 4)));
            size_t gofs = (size_t)(col0 + r) * H256 + kc * 64 + c8 * 8;
            cp16(bh + off, Bhi + gofs);
            cp16(bl + off, Blo + gofs);
        }
    };
    auto loadA1 = [&](int kc, int st) {        // mode 1: bf16 split via cp.async
        uint32_t ah = sb + A_ST(st), al = ah + 8192u;
#pragma unroll
        for (int it = 0; it < 2; it++) {
            int idx = tid + it * 256;          // 0..511
            int r = idx >> 3, c8 = idx & 7;
            uint32_t off = (uint32_t)(r * 128 + ((c8 * 16) ^ ((r & 7) << 4)));
            size_t gofs = (size_t)(row0 + r) * H256 + kc * 64 + c8 * 8;
            cp16(ah + off, Ahi + gofs);
            cp16(al + off, Alo + gofs);
        }
    };

    float4 regs[4];
    auto fetchA0 = [&](int kc) {               // mode 0: fp32 -> regs (guarded)
#pragma unroll
        for (int it = 0; it < 4; it++) {
            int idx = tid + it * 256;          // 0..1023 float4 units
            int r = idx >> 4, k4u = idx & 15;
            regs[it] = (row0 + r < Nn)
                ? *(const float4*)(A32 + (size_t)(row0 + r) * H256 + kc * 64 + k4u * 4)
                : make_float4(0.f, 0.f, 0.f, 0.f);
        }
    };
    auto storeA0 = [&](int st) {               // regs -> split bf16 smem
        const uint32_t base = A_ST(st);
#pragma unroll
        for (int it = 0; it < 4; it++) {
            int idx = tid + it * 256;
            int r = idx >> 4, k4u = idx & 15;
            float4 v = regs[it];
            float h0 = __bfloat162float(__float2bfloat16_rn(v.x));
            float h1 = __bfloat162float(__float2bfloat16_rn(v.y));
            float h2 = __bfloat162float(__float2bfloat16_rn(v.z));
            float h3 = __bfloat162float(__float2bfloat16_rn(v.w));
            uint32_t off = (uint32_t)(r * 128 + ((k4u * 8) ^ ((r & 7) << 4)));
            *(uint2*)(smem + base + off) = make_uint2(pack_bf2(h0, h1), pack_bf2(h2, h3));
            *(uint2*)(smem + base + 8192 + off) =
                make_uint2(pack_bf2(v.x - h0, v.y - h1), pack_bf2(v.z - h2, v.w - h3));
        }
    };

    // ---- prologue: chunk 0 in flight ----
    loadB(0, 0);
    if (mode == 1) loadA1(0, 0);
    cp_commit();
    if (mode == 0) fetchA0(0);

#pragma unroll
    for (int kc = 0; kc < 4; kc++) {
        const int st = kc & 1;
        if (mode == 0) storeA0(st);            // safe: stage st idle since sync(kc-1)
        cp_wait<0>();                          // chunk kc async loads arrived
        __syncthreads();                       // all warps done MMA(kc-1)
        if (kc < 3) {                          // next chunk into the other stage
            loadB(kc + 1, st ^ 1);
            if (mode == 1) loadA1(kc + 1, st ^ 1);
            cp_commit();
            if (mode == 0) fetchA0(kc + 1);    // global->regs overlaps MMA
        }

        const uint32_t aH = sb + A_ST(st), aL = aH + 8192u;
        const uint32_t bH = sb + B_ST(st), bL = bH + 16384u;
#pragma unroll
        for (int s = 0; s < 4; s++) {
            const int k0 = s * 16;
            uint32_t ah[2][4], al[2][4], bh[2][4], bl[2][4];
#pragma unroll
            for (int i = 0; i < 2; i++) {
                uint32_t off = aRow[i] + (((uint32_t)((k0 + a_kq) * 2)) ^ aMask[i]);
                ldsm4(ah[i], aH + off);
                ldsm4(al[i], aL + off);
            }
#pragma unroll
            for (int j = 0; j < 2; j++) {
                uint32_t off = bRow[j] + (((uint32_t)((k0 + b_kq) * 2)) ^ bMask[j]);
                ldsm4(bh[j], bH + off);
                ldsm4(bl[j], bL + off);
            }
#pragma unroll
            for (int i = 0; i < 2; i++)
#pragma unroll
                for (int j = 0; j < 2; j++)
#pragma unroll
                    for (int h = 0; h < 2; h++) {
                        const int ns = j * 2 + h;
                        mma_bf16(C[i][ns], ah[i], &bh[j][2 * h]);
                        mma_bf16(C[i][ns], ah[i], &bl[j][2 * h]);
                        mma_bf16(C[i][ns], al[i], &bh[j][2 * h]);
                    }
        }
    }

    // ---- Epilogue ----
    const int rbase = row0 + wm * 32 + (lane >> 2);
    const int cbase = col0 + wn * 32 + (lane & 3) * 2;
    float ss[2][2] = {{0.f, 0.f}, {0.f, 0.f}};

#pragma unroll
    for (int i = 0; i < 2; i++) {
#pragma unroll
        for (int ns = 0; ns < 4; ns++) {
            const int c   = cbase + ns * 8;
            const float bv0 = __ldg(&bias[c]);
            const float bv1 = __ldg(&bias[c + 1]);
#pragma unroll
            for (int rh = 0; rh < 2; rh++) {
                const int r = rbase + i * 16 + rh * 8;
                float v0 = C[i][ns][rh * 2 + 0] + bv0;
                float v1 = C[i][ns][rh * 2 + 1] + bv1;
                const size_t go = (size_t)r * H256 + c;
                if (mode == 0) {
                    v0 = fmaxf(v0, 0.0f);
                    v1 = fmaxf(v1, 0.0f);
                    float h0 = __bfloat162float(__float2bfloat16_rn(v0));
                    float h1 = __bfloat162float(__float2bfloat16_rn(v1));
                    *(uint32_t*)(OutHi + go) = pack_bf2(h0, h1);
                    *(uint32_t*)(OutLo + go) = pack_bf2(v0 - h0, v1 - h1);
                } else {
                    *(uint32_t*)(OutH + go) = pack_h2(v0, v1);
                    ss[i][rh] = fmaf(v0, v0, ss[i][rh]);
                    ss[i][rh] = fmaf(v1, v1, ss[i][rh]);
                }
            }
        }
    }

    if (mode == 1) {
        // Deterministic in-CTA row reduction; plain store to this column
        // tile's partial array (no atomics needed).
        __syncthreads();                       // MMA readers done; reuse smem
        float* red = (float*)smem;             // 64 rows x 4 (wn)
#pragma unroll
        for (int i = 0; i < 2; i++)
#pragma unroll
            for (int rh = 0; rh < 2; rh++) {
                float s = ss[i][rh];
                s += __shfl_xor_sync(0xffffffffu, s, 1);
                s += __shfl_xor_sync(0xffffffffu, s, 2);
                int rl = wm * 32 + (lane >> 2) + i * 16 + rh * 8;
                if ((lane & 3) == 0) red[rl * 4 + wn] = s;
            }
        __syncthreads();
        if (tid < 64) {
            float s = ((red[tid * 4] + red[tid * 4 + 1]) + red[tid * 4 + 2]) + red[tid * 4 + 3];
            sumsq[(size_t)blockIdx.y * NPAD + row0 + tid] = s;
        }
    }
}

// ---------------------------------------------------------------------------
// Prep: split W1/W2 into bf16 hi/lo.
// ---------------------------------------------------------------------------
__global__ __launch_bounds__(256) void prep_w(
    const float* __restrict__ W1, const float* __restrict__ W2,
    __nv_bfloat16* w1h, __nv_bfloat16* w1l,
    __nv_bfloat16* w2h, __nv_bfloat16* w2l)
{
    int i = blockIdx.x * 256 + threadIdx.x;
    if (i < H256 * H256) {
        float a = W1[i];
        __nv_bfloat16 h = __float2bfloat16_rn(a);
        w1h[i] = h;
        w1l[i] = __float2bfloat16_rn(a - __bfloat162float(h));
        float b = W2[i];
        __nv_bfloat16 h2 = __float2bfloat16_rn(b);
        w2h[i] = h2;
        w2l[i] = __float2bfloat16_rn(b - __bfloat162float(h2));
    }
}

// ---------------------------------------------------------------------------
// Edge kernel: 8 lanes per edge, 4 edges per warp, 32 edges per block.
// Per-lane: 64B of each row (4 x uint4), hfma2 chains of depth 4 then fp32
// accumulate; 3-shfl reduction; norms prefetched before the dot.
// ---------------------------------------------------------------------------
__global__ __launch_bounds__(256) void edge_kernel(
    const __half* __restrict__ g16, const float* __restrict__ ssq,
    const int* __restrict__ ei, float* __restrict__ out, int E, int N)
{
    const int tid  = threadIdx.x;
    const int sub  = tid & 7;                       // lane within 8-lane group
    const int e0   = blockIdx.x * 32 + (tid >> 3);  // edge id for this group
    const int e    = min(e0, E - 1);                // clamp: keep lanes active

    int c = ei[e];
    int r = ei[E + e];
    c = min(max(c, 0), N - 1);
    r = min(max(r, 0), N - 1);

    // Prefetch norm partials early (lane 0 of the group only); their ~L2
    // latency overlaps the dot below.
    float sc0 = 0.f, sc1 = 0.f, sr0 = 0.f, sr1 = 0.f;
    if (sub == 0) {
        sc0 = __ldg(ssq + c);
        sc1 = __ldg(ssq + NPAD + c);
        sr0 = __ldg(ssq + r);
        sr1 = __ldg(ssq + NPAD + r);
    }

    const uint4* pa = (const uint4*)(g16 + (size_t)c * H256);
    const uint4* pb = (const uint4*)(g16 + (size_t)r * H256);

    float s = 0.0f;
#pragma unroll
    for (int j = 0; j < 4; j++) {
        uint4 a = pa[sub + j * 8];
        uint4 b = pb[sub + j * 8];
        const __half2* ha = (const __half2*)&a;
        const __half2* hb = (const __half2*)&b;
        __half2 acc = __hmul2(ha[0], hb[0]);        // fp16 chain depth 4
        acc = __hfma2(ha[1], hb[1], acc);
        acc = __hfma2(ha[2], hb[2], acc);
        acc = __hfma2(ha[3], hb[3], acc);
        float2 f = __half22float2(acc);
        s += f.x + f.y;                             // fp32 across chains
    }
    s += __shfl_xor_sync(0xffffffffu, s, 1);
    s += __shfl_xor_sync(0xffffffffu, s, 2);
    s += __shfl_xor_sync(0xffffffffu, s, 4);

    if (sub == 0 && e0 < E) {
        float nc = fmaxf(sqrtf(sc0 + sc1), 1e-8f);
        float nr = fmaxf(sqrtf(sr0 + sr1), 1e-8f);
        out[e0] = s / (nc * nr);
    }
}

// ---------------------------------------------------------------------------
extern "C" void kernel_launch(void* const* d_in, const int* in_sizes, int n_in,
                              void* d_out, int out_size)
{
    const float* emb = (const float*)d_in[0];
    const int*   ei  = (const int*)d_in[1];
    const float* W1  = (const float*)d_in[2];
    const float* b1  = (const float*)d_in[3];
    const float* W2  = (const float*)d_in[4];
    const float* b2  = (const float*)d_in[5];
    float*       out = (float*)d_out;

    const int Hn = in_sizes[3];
    const int N  = in_sizes[0] / Hn;
    const int E  = in_sizes[1] / 2;
    if (Hn != H256 || N > NPAD) return;

    float* ssbuf;
    __half* g16;
    __nv_bfloat16 *hhi, *hlo, *w1h, *w1l, *w2h, *w2l;
    cudaGetSymbolAddress((void**)&g16,   g_g16);
    cudaGetSymbolAddress((void**)&hhi,   g_h_hi);
    cudaGetSymbolAddress((void**)&hlo,   g_h_lo);
    cudaGetSymbolAddress((void**)&w1h,   g_w1_hi);
    cudaGetSymbolAddress((void**)&w1l,   g_w1_lo);
    cudaGetSymbolAddress((void**)&w2h,   g_w2_hi);
    cudaGetSymbolAddress((void**)&w2l,   g_w2_lo);
    cudaGetSymbolAddress((void**)&ssbuf, g_sumsq);

    cudaFuncSetAttribute(gemm_hmma, cudaFuncAttributeMaxDynamicSharedMemorySize, SMEM_BYTES);

    prep_w<<<(H256 * H256 + 255) / 256, 256>>>(W1, W2, w1h, w1l, w2h, w2l);

    dim3 ggrid(NPAD / 64, 2);
    // Layer 1: h = relu(emb @ W1^T + b1), emb split on the fly, h stored split
    gemm_hmma<<<ggrid, 256, SMEM_BYTES>>>(emb, nullptr, nullptr, w1h, w1l, b1, N, 0,
                                          hhi, hlo, nullptr, nullptr);
    // Layer 2: g = h @ W2^T + b2 -> fp16 table + fp32 row sumsq parts
    gemm_hmma<<<ggrid, 256, SMEM_BYTES>>>(nullptr, hhi, hlo, w2h, w2l, b2, N, 1,
                                          nullptr, nullptr, g16, ssbuf);
    // Per-edge cosine: 32 edges per 256-thread block
    edge_kernel<<<(E + 31) / 32, 256>>>(g16, ssbuf, ei, out, E, N);
}

// round 12
// speedup vs baseline: 1.2277x; 1.0129x over previous
#include <cuda_runtime.h>
#include <cuda_bf16.h>
#include <cuda_fp16.h>
#include <cstdint>
#include <math.h>

// N=50000, H=256, E=300000.
// g = MLP(emb) once over nodes (exact restructure), per-edge cosine gather.
// GEMMs: warp-level HMMA (mma.sync bf16; tcgen05 unavailable on this
// harness's compute_103 target). Split precision 3-product.
// This round: PERSISTENT gemm CTAs (296 = 2/SM), flat pipelined chunk stream
// across row-tiles — removes wave-quantization tail and per-CTA prologues.

#define H256 256
#define NPAD 50176   // 784*64
#define NT_ROW 784   // row tiles of 64
#define RT_STRIDE 148

// ---------------- device scratch (allocation-free) ----------------
__device__ __align__(16) __half         g_g16[(size_t)NPAD * H256];   // g as fp16
__device__ __align__(16) __nv_bfloat16  g_h_hi[(size_t)NPAD * H256];
__device__ __align__(16) __nv_bfloat16  g_h_lo[(size_t)NPAD * H256];
__device__ __align__(16) __nv_bfloat16  g_w1_hi[H256 * H256];
__device__ __align__(16) __nv_bfloat16  g_w1_lo[H256 * H256];
__device__ __align__(16) __nv_bfloat16  g_w2_hi[H256 * H256];
__device__ __align__(16) __nv_bfloat16  g_w2_lo[H256 * H256];
__device__ float g_sumsq[2 * NPAD];     // per-column-tile partial row sumsq

// ---------------- PTX helpers ----------------
__device__ __forceinline__ uint32_t smem_u32(const void* p) {
    uint32_t a;
    asm("{ .reg .u64 t; cvta.to.shared.u64 t, %1; cvt.u32.u64 %0, t; }" : "=r"(a) : "l"(p));
    return a;
}
__device__ __forceinline__ void cp16(uint32_t s, const void* g) {
    asm volatile("cp.async.cg.shared.global [%0], [%1], 16;"
                 :: "r"(s), "l"(__cvta_generic_to_global(g)) : "memory");
}
__device__ __forceinline__ void cp_commit() {
    asm volatile("cp.async.commit_group;" ::: "memory");
}
template <int NN>
__device__ __forceinline__ void cp_wait() {
    asm volatile("cp.async.wait_group %0;" :: "n"(NN) : "memory");
}
__device__ __forceinline__ void ldsm4(uint32_t* r, uint32_t addr) {
    asm volatile("ldmatrix.sync.aligned.m8n8.x4.shared.b16 {%0,%1,%2,%3}, [%4];"
                 : "=r"(r[0]), "=r"(r[1]), "=r"(r[2]), "=r"(r[3]) : "r"(addr));
}
__device__ __forceinline__ void mma_bf16(float* c, const uint32_t* a, const uint32_t* b) {
    asm volatile(
        "mma.sync.aligned.m16n8k16.row.col.f32.bf16.bf16.f32 "
        "{%0,%1,%2,%3}, {%4,%5,%6,%7}, {%8,%9}, {%0,%1,%2,%3};"
        : "+f"(c[0]), "+f"(c[1]), "+f"(c[2]), "+f"(c[3])
        : "r"(a[0]), "r"(a[1]), "r"(a[2]), "r"(a[3]), "r"(b[0]), "r"(b[1]));
}
__device__ __forceinline__ uint32_t pack_bf2(float a, float b) {
    __nv_bfloat162 t = __floats2bfloat162_rn(a, b);
    return *reinterpret_cast<uint32_t*>(&t);
}
__device__ __forceinline__ uint32_t pack_h2(float a, float b) {
    __half2 t = __floats2half2_rn(a, b);
    return *reinterpret_cast<uint32_t*>(&t);
}

// SMEM (per-CTA):
//  A stage st: base st*16384; hi +0 (8KB: 64r x 64k bf16), lo +8192
//  B stage st: base 32768 + st*32768; hi +0 (16KB: 128r x 64k), lo +16384
//  RED: 1KB reduction scratch at 98304 (A/B stay live mid-stream)
#define A_ST(st)  ((uint32_t)(st) * 16384u)
#define B_ST(st)  (32768u + (uint32_t)(st) * 32768u)
#define RED_OFF   98304
#define SMEM_BYTES 99328

// ---------------------------------------------------------------------------
// Persistent HMMA split-bf16 GEMM. 296 CTAs (2/SM), 256 thr (8 warps,
// 2m x 4n of 32x32). Each CTA: fixed col half, row-tiles strided by 148,
// K=256 in 4 chunks of 64, one flat double-buffered chunk pipeline.
// mode 0: A = fp32 (split on the fly, reg-staged); out = relu(C+bias) split.
// mode 1: A = bf16 hi/lo (cp.async); out = fp16 C+bias + fp32 row sumsq part.
// ---------------------------------------------------------------------------
__global__ __launch_bounds__(256, 2) void gemm_hmma(
    const float* __restrict__ A32,
    const __nv_bfloat16* __restrict__ Ahi, const __nv_bfloat16* __restrict__ Alo,
    const __nv_bfloat16* __restrict__ Bhi, const __nv_bfloat16* __restrict__ Blo,
    const float* __restrict__ bias, int Nn, int mode,
    __nv_bfloat16* __restrict__ OutHi, __nv_bfloat16* __restrict__ OutLo,
    __half* __restrict__ OutH, float* __restrict__ sumsq)
{
    extern __shared__ char smem[];
    const uint32_t sb = smem_u32(smem);
    const int tid  = threadIdx.x;
    const int lane = tid & 31, wid = tid >> 5;
    const int wm = wid & 1, wn = wid >> 1;        // 2 x 4 warp grid (32x32 tiles)
    const int colSel = blockIdx.x & 1;
    const int col0 = colSel * 128;
    const int rt0  = blockIdx.x >> 1;             // 0..147

    float C[2][4][4];
#pragma unroll
    for (int i = 0; i < 2; i++)
#pragma unroll
        for (int j = 0; j < 4; j++)
#pragma unroll
            for (int q = 0; q < 4; q++) C[i][j][q] = 0.0f;

    // ---- ldmatrix lane addressing (row0-independent) ----
    const int a_r  = wm * 32 + (lane & 7) + ((lane >> 3) & 1) * 8;
    const int a_kq = ((lane >> 4) & 1) * 8;
    const int b_n  = wn * 32 + (lane & 7) + ((lane >> 4) & 1) * 8;
    const int b_kq = ((lane >> 3) & 1) * 8;
    uint32_t aRow[2], aMask[2], bRow[2], bMask[2];
#pragma unroll
    for (int i = 0; i < 2; i++) {
        int r = a_r + i * 16;
        aRow[i]  = (uint32_t)(r * 128);
        aMask[i] = (uint32_t)((r & 7) << 4);
    }
#pragma unroll
    for (int j = 0; j < 2; j++) {
        int n = b_n + j * 16;
        bRow[j]  = (uint32_t)(n * 128);
        bMask[j] = (uint32_t)((n & 7) << 4);
    }

    // ---- loader helpers ----
    auto loadB = [&](int kc, int st) {
        uint32_t bh = sb + B_ST(st), bl = bh + 16384u;
#pragma unroll
        for (int it = 0; it < 4; it++) {
            int idx = tid + it * 256;          // 0..1023
            int r = idx >> 3, c8 = idx & 7;
            uint32_t off = (uint32_t)(r * 128 + ((c8 * 16) ^ ((r & 7) << 4)));
            size_t gofs = (size_t)(col0 + r) * H256 + kc * 64 + c8 * 8;
            cp16(bh + off, Bhi + gofs);
            cp16(bl + off, Blo + gofs);
        }
    };
    auto loadA1 = [&](int row0, int kc, int st) {  // mode 1: bf16 split cp.async
        uint32_t ah = sb + A_ST(st), al = ah + 8192u;
#pragma unroll
        for (int it = 0; it < 2; it++) {
            int idx = tid + it * 256;          // 0..511
            int r = idx >> 3, c8 = idx & 7;
            uint32_t off = (uint32_t)(r * 128 + ((c8 * 16) ^ ((r & 7) << 4)));
            size_t gofs = (size_t)(row0 + r) * H256 + kc * 64 + c8 * 8;
            cp16(ah + off, Ahi + gofs);
            cp16(al + off, Alo + gofs);
        }
    };

    float4 regs[4];
    auto fetchA0 = [&](int row0, int kc) {     // mode 0: fp32 -> regs (guarded)
#pragma unroll
        for (int it = 0; it < 4; it++) {
            int idx = tid + it * 256;          // 0..1023 float4 units
            int r = idx >> 4, k4u = idx & 15;
            regs[it] = (row0 + r < Nn)
                ? *(const float4*)(A32 + (size_t)(row0 + r) * H256 + kc * 64 + k4u * 4)
                : make_float4(0.f, 0.f, 0.f, 0.f);
        }
    };
    auto storeA0 = [&](int st) {               // regs -> split bf16 smem
        const uint32_t base = A_ST(st);
#pragma unroll
        for (int it = 0; it < 4; it++) {
            int idx = tid + it * 256;
            int r = idx >> 4, k4u = idx & 15;
            float4 v = regs[it];
            float h0 = __bfloat162float(__float2bfloat16_rn(v.x));
            float h1 = __bfloat162float(__float2bfloat16_rn(v.y));
            float h2 = __bfloat162float(__float2bfloat16_rn(v.z));
            float h3 = __bfloat162float(__float2bfloat16_rn(v.w));
            uint32_t off = (uint32_t)(r * 128 + ((k4u * 8) ^ ((r & 7) << 4)));
            *(uint2*)(smem + base + off) = make_uint2(pack_bf2(h0, h1), pack_bf2(h2, h3));
            *(uint2*)(smem + base + 8192 + off) =
                make_uint2(pack_bf2(v.x - h0, v.y - h1), pack_bf2(v.z - h2, v.w - h3));
        }
    };

    // ---- prologue: first chunk of first tile in flight ----
    {
        int row0 = rt0 * 64;
        loadB(0, 0);
        if (mode == 1) loadA1(row0, 0, 0);
        cp_commit();
        if (mode == 0) fetchA0(row0, 0);
    }

    int q = 0;                                  // flat chunk counter
    for (int rt = rt0; rt < NT_ROW; rt += RT_STRIDE) {
        const int row0 = rt * 64;
#pragma unroll
        for (int kc = 0; kc < 4; kc++, q++) {
            const int st = q & 1;
            if (mode == 0) storeA0(st);
            cp_wait<0>();                       // chunk q arrived
            __syncthreads();                    // all warps done MMA(q-1)

            // issue chunk q+1 (possibly next tile's chunk 0)
            const bool last = (kc == 3) && (rt + RT_STRIDE >= NT_ROW);
            if (!last) {
                const int nkc   = (kc + 1) & 3;
                const int nrow0 = (kc == 3) ? (rt + RT_STRIDE) * 64 : row0;
                loadB(nkc, st ^ 1);
                if (mode == 1) loadA1(nrow0, nkc, st ^ 1);
                cp_commit();
                if (mode == 0) fetchA0(nrow0, nkc);
            }

            const uint32_t aH = sb + A_ST(st), aL = aH + 8192u;
            const uint32_t bH = sb + B_ST(st), bL = bH + 16384u;
#pragma unroll
            for (int s = 0; s < 4; s++) {
                const int k0 = s * 16;
                uint32_t ah[2][4], al[2][4], bh[2][4], bl[2][4];
#pragma unroll
                for (int i = 0; i < 2; i++) {
                    uint32_t off = aRow[i] + (((uint32_t)((k0 + a_kq) * 2)) ^ aMask[i]);
                    ldsm4(ah[i], aH + off);
                    ldsm4(al[i], aL + off);
                }
#pragma unroll
                for (int j = 0; j < 2; j++) {
                    uint32_t off = bRow[j] + (((uint32_t)((k0 + b_kq) * 2)) ^ bMask[j]);
                    ldsm4(bh[j], bH + off);
                    ldsm4(bl[j], bL + off);
                }
#pragma unroll
                for (int i = 0; i < 2; i++)
#pragma unroll
                    for (int j = 0; j < 2; j++)
#pragma unroll
                        for (int h = 0; h < 2; h++) {
                            const int ns = j * 2 + h;
                            mma_bf16(C[i][ns], ah[i], &bh[j][2 * h]);
                            mma_bf16(C[i][ns], ah[i], &bl[j][2 * h]);
                            mma_bf16(C[i][ns], al[i], &bh[j][2 * h]);
                        }
            }
        }

        // ---- Epilogue for this row-tile ----
        const int rbase = row0 + wm * 32 + (lane >> 2);
        const int cbase = col0 + wn * 32 + (lane & 3) * 2;
        float ss[2][2] = {{0.f, 0.f}, {0.f, 0.f}};

#pragma unroll
        for (int i = 0; i < 2; i++) {
#pragma unroll
            for (int ns = 0; ns < 4; ns++) {
                const int c   = cbase + ns * 8;
                const float bv0 = __ldg(&bias[c]);
                const float bv1 = __ldg(&bias[c + 1]);
#pragma unroll
                for (int rh = 0; rh < 2; rh++) {
                    const int r = rbase + i * 16 + rh * 8;
                    float v0 = C[i][ns][rh * 2 + 0] + bv0;
                    float v1 = C[i][ns][rh * 2 + 1] + bv1;
                    const size_t go = (size_t)r * H256 + c;
                    if (mode == 0) {
                        v0 = fmaxf(v0, 0.0f);
                        v1 = fmaxf(v1, 0.0f);
                        float h0 = __bfloat162float(__float2bfloat16_rn(v0));
                        float h1 = __bfloat162float(__float2bfloat16_rn(v1));
                        *(uint32_t*)(OutHi + go) = pack_bf2(h0, h1);
                        *(uint32_t*)(OutLo + go) = pack_bf2(v0 - h0, v1 - h1);
                    } else {
                        *(uint32_t*)(OutH + go) = pack_h2(v0, v1);
                        ss[i][rh] = fmaf(v0, v0, ss[i][rh]);
                        ss[i][rh] = fmaf(v1, v1, ss[i][rh]);
                    }
                }
            }
        }

        if (mode == 1) {
            // Deterministic in-CTA row reduction into dedicated smem region.
            float* red = (float*)(smem + RED_OFF);   // 64 rows x 4 (wn)
            __syncthreads();
#pragma unroll
            for (int i = 0; i < 2; i++)
#pragma unroll
                for (int rh = 0; rh < 2; rh++) {
                    float s = ss[i][rh];
                    s += __shfl_xor_sync(0xffffffffu, s, 1);
                    s += __shfl_xor_sync(0xffffffffu, s, 2);
                    int rl = wm * 32 + (lane >> 2) + i * 16 + rh * 8;
                    if ((lane & 3) == 0) red[rl * 4 + wn] = s;
                }
            __syncthreads();
            if (tid < 64) {
                float s = ((red[tid * 4] + red[tid * 4 + 1]) + red[tid * 4 + 2]) + red[tid * 4 + 3];
                sumsq[(size_t)colSel * NPAD + row0 + tid] = s;
            }
        }

        // reset accumulators for next tile
#pragma unroll
        for (int i = 0; i < 2; i++)
#pragma unroll
            for (int j = 0; j < 4; j++)
#pragma unroll
                for (int p = 0; p < 4; p++) C[i][j][p] = 0.0f;
    }
}

// ---------------------------------------------------------------------------
// Prep: split W1/W2 into bf16 hi/lo.
// ---------------------------------------------------------------------------
__global__ __launch_bounds__(256) void prep_w(
    const float* __restrict__ W1, const float* __restrict__ W2,
    __nv_bfloat16* w1h, __nv_bfloat16* w1l,
    __nv_bfloat16* w2h, __nv_bfloat16* w2l)
{
    int i = blockIdx.x * 256 + threadIdx.x;
    if (i < H256 * H256) {
        float a = W1[i];
        __nv_bfloat16 h = __float2bfloat16_rn(a);
        w1h[i] = h;
        w1l[i] = __float2bfloat16_rn(a - __bfloat162float(h));
        float b = W2[i];
        __nv_bfloat16 h2 = __float2bfloat16_rn(b);
        w2h[i] = h2;
        w2l[i] = __float2bfloat16_rn(b - __bfloat162float(h2));
    }
}

// ---------------------------------------------------------------------------
// Edge kernel: 8 lanes per edge, 4 edges per warp, 32 edges per block.
// hfma2 chains of depth 4, fp32 across chains; 3-shfl reduction; norm
// partials prefetched before the dot.
// ---------------------------------------------------------------------------
__global__ __launch_bounds__(256) void edge_kernel(
    const __half* __restrict__ g16, const float* __restrict__ ssq,
    const int* __restrict__ ei, float* __restrict__ out, int E, int N)
{
    const int tid  = threadIdx.x;
    const int sub  = tid & 7;                       // lane within 8-lane group
    const int e0   = blockIdx.x * 32 + (tid >> 3);  // edge id for this group
    const int e    = min(e0, E - 1);                // clamp: keep lanes active

    int c = ei[e];
    int r = ei[E + e];
    c = min(max(c, 0), N - 1);
    r = min(max(r, 0), N - 1);

    float sc0 = 0.f, sc1 = 0.f, sr0 = 0.f, sr1 = 0.f;
    if (sub == 0) {
        sc0 = __ldg(ssq + c);
        sc1 = __ldg(ssq + NPAD + c);
        sr0 = __ldg(ssq + r);
        sr1 = __ldg(ssq + NPAD + r);
    }

    const uint4* pa = (const uint4*)(g16 + (size_t)c * H256);
    const uint4* pb = (const uint4*)(g16 + (size_t)r * H256);

    float s = 0.0f;
#pragma unroll
    for (int j = 0; j < 4; j++) {
        uint4 a = pa[sub + j * 8];
        uint4 b = pb[sub + j * 8];
        const __half2* ha = (const __half2*)&a;
        const __half2* hb = (const __half2*)&b;
        __half2 acc = __hmul2(ha[0], hb[0]);        // fp16 chain depth 4
        acc = __hfma2(ha[1], hb[1], acc);
        acc = __hfma2(ha[2], hb[2], acc);
        acc = __hfma2(ha[3], hb[3], acc);
        float2 f = __half22float2(acc);
        s += f.x + f.y;                             // fp32 across chains
    }
    s += __shfl_xor_sync(0xffffffffu, s, 1);
    s += __shfl_xor_sync(0xffffffffu, s, 2);
    s += __shfl_xor_sync(0xffffffffu, s, 4);

    if (sub == 0 && e0 < E) {
        float nc = fmaxf(sqrtf(sc0 + sc1), 1e-8f);
        float nr = fmaxf(sqrtf(sr0 + sr1), 1e-8f);
        out[e0] = s / (nc * nr);
    }
}

// ---------------------------------------------------------------------------
extern "C" void kernel_launch(void* const* d_in, const int* in_sizes, int n_in,
                              void* d_out, int out_size)
{
    const float* emb = (const float*)d_in[0];
    const int*   ei  = (const int*)d_in[1];
    const float* W1  = (const float*)d_in[2];
    const float* b1  = (const float*)d_in[3];
    const float* W2  = (const float*)d_in[4];
    const float* b2  = (const float*)d_in[5];
    float*       out = (float*)d_out;

    const int Hn = in_sizes[3];
    const int N  = in_sizes[0] / Hn;
    const int E  = in_sizes[1] / 2;
    if (Hn != H256 || N > NPAD) return;

    float* ssbuf;
    __half* g16;
    __nv_bfloat16 *hhi, *hlo, *w1h, *w1l, *w2h, *w2l;
    cudaGetSymbolAddress((void**)&g16,   g_g16);
    cudaGetSymbolAddress((void**)&hhi,   g_h_hi);
    cudaGetSymbolAddress((void**)&hlo,   g_h_lo);
    cudaGetSymbolAddress((void**)&w1h,   g_w1_hi);
    cudaGetSymbolAddress((void**)&w1l,   g_w1_lo);
    cudaGetSymbolAddress((void**)&w2h,   g_w2_hi);
    cudaGetSymbolAddress((void**)&w2l,   g_w2_lo);
    cudaGetSymbolAddress((void**)&ssbuf, g_sumsq);

    cudaFuncSetAttribute(gemm_hmma, cudaFuncAttributeMaxDynamicSharedMemorySize, SMEM_BYTES);

    prep_w<<<(H256 * H256 + 255) / 256, 256>>>(W1, W2, w1h, w1l, w2h, w2l);

    // Persistent: 296 CTAs (2/SM), each owns a col half + strided row tiles.
    gemm_hmma<<<2 * RT_STRIDE, 256, SMEM_BYTES>>>(emb, nullptr, nullptr, w1h, w1l, b1, N, 0,
                                                  hhi, hlo, nullptr, nullptr);
    gemm_hmma<<<2 * RT_STRIDE, 256, SMEM_BYTES>>>(nullptr, hhi, hlo, w2h, w2l, b2, N, 1,
                                                  nullptr, nullptr, g16, ssbuf);
    edge_kernel<<<(E + 31) / 32, 256>>>(g16, ssbuf, ei, out, E, N);
}

// round 13
// speedup vs baseline: 2.0126x; 1.6393x over previous
#include <cuda_runtime.h>
#include <cuda_bf16.h>
#include <cuda_fp16.h>
#include <cstdint>
#include <math.h>

// N=50000, H=256, E=300000.
// g = MLP(emb) once over nodes (exact restructure), per-edge cosine gather.
// GEMMs: warp-level HMMA, SINGLE-PRODUCT fp16 (calibrated: cosine averages
// per-element rounding ~8x; predicted contribution ~6e-5/layer). 3x fewer
// MMAs and half the load traffic vs the split-bf16 scheme.

#define H256 256
#define NPAD 50176   // 784*64
#define NT_ROW 784   // row tiles of 64
#define RT_STRIDE 148

// ---------------- device scratch (allocation-free) ----------------
__device__ __align__(16) __half g_g16[(size_t)NPAD * H256];   // g as fp16
__device__ __align__(16) __half g_h16[(size_t)NPAD * H256];   // h as fp16
__device__ __align__(16) __half g_w1[H256 * H256];
__device__ __align__(16) __half g_w2[H256 * H256];
__device__ float g_sumsq[2 * NPAD];     // per-column-tile partial row sumsq

// ---------------- PTX helpers ----------------
__device__ __forceinline__ uint32_t smem_u32(const void* p) {
    uint32_t a;
    asm("{ .reg .u64 t; cvta.to.shared.u64 t, %1; cvt.u32.u64 %0, t; }" : "=r"(a) : "l"(p));
    return a;
}
__device__ __forceinline__ void cp16(uint32_t s, const void* g) {
    asm volatile("cp.async.cg.shared.global [%0], [%1], 16;"
                 :: "r"(s), "l"(__cvta_generic_to_global(g)) : "memory");
}
__device__ __forceinline__ void cp_commit() {
    asm volatile("cp.async.commit_group;" ::: "memory");
}
template <int NN>
__device__ __forceinline__ void cp_wait() {
    asm volatile("cp.async.wait_group %0;" :: "n"(NN) : "memory");
}
__device__ __forceinline__ void ldsm4(uint32_t* r, uint32_t addr) {
    asm volatile("ldmatrix.sync.aligned.m8n8.x4.shared.b16 {%0,%1,%2,%3}, [%4];"
                 : "=r"(r[0]), "=r"(r[1]), "=r"(r[2]), "=r"(r[3]) : "r"(addr));
}
__device__ __forceinline__ void mma_f16(float* c, const uint32_t* a, const uint32_t* b) {
    asm volatile(
        "mma.sync.aligned.m16n8k16.row.col.f32.f16.f16.f32 "
        "{%0,%1,%2,%3}, {%4,%5,%6,%7}, {%8,%9}, {%0,%1,%2,%3};"
        : "+f"(c[0]), "+f"(c[1]), "+f"(c[2]), "+f"(c[3])
        : "r"(a[0]), "r"(a[1]), "r"(a[2]), "r"(a[3]), "r"(b[0]), "r"(b[1]));
}
__device__ __forceinline__ uint32_t pack_h2(float a, float b) {
    __half2 t = __floats2half2_rn(a, b);
    return *reinterpret_cast<uint32_t*>(&t);
}

// SMEM (per-CTA ~49KB):
//  A stage st: base st*8192 (8KB: 64r x 64k fp16, 128B/row XOR-swizzled)
//  B stage st: 16384 + st*16384 (16KB: 128r x 64k fp16)
//  RED: 1KB reduction scratch
#define A_ST(st)  ((uint32_t)(st) * 8192u)
#define B_ST(st)  (16384u + (uint32_t)(st) * 16384u)
#define RED_OFF   49152
#define SMEM_BYTES 50176

// ---------------------------------------------------------------------------
// Persistent single-product fp16 HMMA GEMM. 296 CTAs (2/SM), 256 thr
// (8 warps, 2m x 4n of 32x32). Fixed col half, row tiles strided by 148,
// K=256 in 4 chunks of 64, flat double-buffered chunk pipeline.
// mode 0: A = fp32 (converted on the fly); out = fp16 relu(C+bias).
// mode 1: A = fp16 (cp.async); out = fp16 C+bias + fp32 row sumsq part.
// ---------------------------------------------------------------------------
__global__ __launch_bounds__(256, 2) void gemm_hmma(
    const float* __restrict__ A32, const __half* __restrict__ A16,
    const __half* __restrict__ B16,
    const float* __restrict__ bias, int Nn, int mode,
    __half* __restrict__ OutH, float* __restrict__ sumsq)
{
    extern __shared__ char smem[];
    const uint32_t sb = smem_u32(smem);
    const int tid  = threadIdx.x;
    const int lane = tid & 31, wid = tid >> 5;
    const int wm = wid & 1, wn = wid >> 1;        // 2 x 4 warp grid (32x32 tiles)
    const int colSel = blockIdx.x & 1;
    const int col0 = colSel * 128;
    const int rt0  = blockIdx.x >> 1;             // 0..147

    float C[2][4][4];
#pragma unroll
    for (int i = 0; i < 2; i++)
#pragma unroll
        for (int j = 0; j < 4; j++)
#pragma unroll
            for (int q = 0; q < 4; q++) C[i][j][q] = 0.0f;

    // ---- ldmatrix lane addressing ----
    const int a_r  = wm * 32 + (lane & 7) + ((lane >> 3) & 1) * 8;
    const int a_kq = ((lane >> 4) & 1) * 8;
    const int b_n  = wn * 32 + (lane & 7) + ((lane >> 4) & 1) * 8;
    const int b_kq = ((lane >> 3) & 1) * 8;
    uint32_t aRow[2], aMask[2], bRow[2], bMask[2];
#pragma unroll
    for (int i = 0; i < 2; i++) {
        int r = a_r + i * 16;
        aRow[i]  = (uint32_t)(r * 128);
        aMask[i] = (uint32_t)((r & 7) << 4);
    }
#pragma unroll
    for (int j = 0; j < 2; j++) {
        int n = b_n + j * 16;
        bRow[j]  = (uint32_t)(n * 128);
        bMask[j] = (uint32_t)((n & 7) << 4);
    }

    // ---- loader helpers ----
    auto loadB = [&](int kc, int st) {
        uint32_t bb = sb + B_ST(st);
#pragma unroll
        for (int it = 0; it < 4; it++) {
            int idx = tid + it * 256;          // 0..1023
            int r = idx >> 3, c8 = idx & 7;
            uint32_t off = (uint32_t)(r * 128 + ((c8 * 16) ^ ((r & 7) << 4)));
            cp16(bb + off, B16 + (size_t)(col0 + r) * H256 + kc * 64 + c8 * 8);
        }
    };
    auto loadA1 = [&](int row0, int kc, int st) {  // mode 1: fp16 cp.async
        uint32_t ab = sb + A_ST(st);
#pragma unroll
        for (int it = 0; it < 2; it++) {
            int idx = tid + it * 256;          // 0..511
            int r = idx >> 3, c8 = idx & 7;
            uint32_t off = (uint32_t)(r * 128 + ((c8 * 16) ^ ((r & 7) << 4)));
            cp16(ab + off, A16 + (size_t)(row0 + r) * H256 + kc * 64 + c8 * 8);
        }
    };

    float4 regs[4];
    auto fetchA0 = [&](int row0, int kc) {     // mode 0: fp32 -> regs (guarded)
#pragma unroll
        for (int it = 0; it < 4; it++) {
            int idx = tid + it * 256;          // 0..1023 float4 units
            int r = idx >> 4, k4u = idx & 15;
            regs[it] = (row0 + r < Nn)
                ? *(const float4*)(A32 + (size_t)(row0 + r) * H256 + kc * 64 + k4u * 4)
                : make_float4(0.f, 0.f, 0.f, 0.f);
        }
    };
    auto storeA0 = [&](int st) {               // regs -> fp16 smem
        const uint32_t base = A_ST(st);
#pragma unroll
        for (int it = 0; it < 4; it++) {
            int idx = tid + it * 256;
            int r = idx >> 4, k4u = idx & 15;
            float4 v = regs[it];
            uint32_t off = (uint32_t)(r * 128 + ((k4u * 8) ^ ((r & 7) << 4)));
            *(uint2*)(smem + base + off) =
                make_uint2(pack_h2(v.x, v.y), pack_h2(v.z, v.w));
        }
    };

    // ---- prologue: first chunk of first tile in flight ----
    {
        int row0 = rt0 * 64;
        loadB(0, 0);
        if (mode == 1) loadA1(row0, 0, 0);
        cp_commit();
        if (mode == 0) fetchA0(row0, 0);
    }

    int q = 0;                                  // flat chunk counter
    for (int rt = rt0; rt < NT_ROW; rt += RT_STRIDE) {
        const int row0 = rt * 64;
#pragma unroll
        for (int kc = 0; kc < 4; kc++, q++) {
            const int st = q & 1;
            if (mode == 0) storeA0(st);
            cp_wait<0>();                       // chunk q arrived
            __syncthreads();                    // all warps done MMA(q-1)

            const bool last = (kc == 3) && (rt + RT_STRIDE >= NT_ROW);
            if (!last) {
                const int nkc   = (kc + 1) & 3;
                const int nrow0 = (kc == 3) ? (rt + RT_STRIDE) * 64 : row0;
                loadB(nkc, st ^ 1);
                if (mode == 1) loadA1(nrow0, nkc, st ^ 1);
                cp_commit();
                if (mode == 0) fetchA0(nrow0, nkc);
            }

            const uint32_t aB = sb + A_ST(st);
            const uint32_t bB = sb + B_ST(st);
#pragma unroll
            for (int s = 0; s < 4; s++) {
                const int k0 = s * 16;
                uint32_t ah[2][4], bh[2][4];
#pragma unroll
                for (int i = 0; i < 2; i++) {
                    uint32_t off = aRow[i] + (((uint32_t)((k0 + a_kq) * 2)) ^ aMask[i]);
                    ldsm4(ah[i], aB + off);
                }
#pragma unroll
                for (int j = 0; j < 2; j++) {
                    uint32_t off = bRow[j] + (((uint32_t)((k0 + b_kq) * 2)) ^ bMask[j]);
                    ldsm4(bh[j], bB + off);
                }
#pragma unroll
                for (int i = 0; i < 2; i++)
#pragma unroll
                    for (int j = 0; j < 2; j++)
#pragma unroll
                        for (int h = 0; h < 2; h++)
                            mma_f16(C[i][j * 2 + h], ah[i], &bh[j][2 * h]);
            }
        }

        // ---- Epilogue for this row-tile ----
        const int rbase = row0 + wm * 32 + (lane >> 2);
        const int cbase = col0 + wn * 32 + (lane & 3) * 2;
        float ss[2][2] = {{0.f, 0.f}, {0.f, 0.f}};

#pragma unroll
        for (int i = 0; i < 2; i++) {
#pragma unroll
            for (int ns = 0; ns < 4; ns++) {
                const int c   = cbase + ns * 8;
                const float bv0 = __ldg(&bias[c]);
                const float bv1 = __ldg(&bias[c + 1]);
#pragma unroll
                for (int rh = 0; rh < 2; rh++) {
                    const int r = rbase + i * 16 + rh * 8;
                    float v0 = C[i][ns][rh * 2 + 0] + bv0;
                    float v1 = C[i][ns][rh * 2 + 1] + bv1;
                    const size_t go = (size_t)r * H256 + c;
                    if (mode == 0) {
                        v0 = fmaxf(v0, 0.0f);
                        v1 = fmaxf(v1, 0.0f);
                        *(uint32_t*)(OutH + go) = pack_h2(v0, v1);
                    } else {
                        *(uint32_t*)(OutH + go) = pack_h2(v0, v1);
                        ss[i][rh] = fmaf(v0, v0, ss[i][rh]);
                        ss[i][rh] = fmaf(v1, v1, ss[i][rh]);
                    }
                }
            }
        }

        if (mode == 1) {
            // Deterministic in-CTA row reduction into dedicated smem region.
            float* red = (float*)(smem + RED_OFF);   // 64 rows x 4 (wn)
            __syncthreads();
#pragma unroll
            for (int i = 0; i < 2; i++)
#pragma unroll
                for (int rh = 0; rh < 2; rh++) {
                    float s = ss[i][rh];
                    s += __shfl_xor_sync(0xffffffffu, s, 1);
                    s += __shfl_xor_sync(0xffffffffu, s, 2);
                    int rl = wm * 32 + (lane >> 2) + i * 16 + rh * 8;
                    if ((lane & 3) == 0) red[rl * 4 + wn] = s;
                }
            __syncthreads();
            if (tid < 64) {
                float s = ((red[tid * 4] + red[tid * 4 + 1]) + red[tid * 4 + 2]) + red[tid * 4 + 3];
                sumsq[(size_t)colSel * NPAD + row0 + tid] = s;
            }
        }

        // reset accumulators for next tile
#pragma unroll
        for (int i = 0; i < 2; i++)
#pragma unroll
            for (int j = 0; j < 4; j++)
#pragma unroll
                for (int p = 0; p < 4; p++) C[i][j][p] = 0.0f;
    }
}

// ---------------------------------------------------------------------------
// Prep: convert W1/W2 to fp16.
// ---------------------------------------------------------------------------
__global__ __launch_bounds__(256) void prep_w(
    const float* __restrict__ W1, const float* __restrict__ W2,
    __half* w1, __half* w2)
{
    int i = blockIdx.x * 256 + threadIdx.x;
    if (i < H256 * H256) {
        w1[i] = __float2half_rn(W1[i]);
        w2[i] = __float2half_rn(W2[i]);
    }
}

// ---------------------------------------------------------------------------
// Edge kernel: 8 lanes per edge, 4 edges per warp, 32 edges per block.
// hfma2 chains of depth 4, fp32 across chains; 3-shfl reduction; norm
// partials prefetched before the dot.
// ---------------------------------------------------------------------------
__global__ __launch_bounds__(256) void edge_kernel(
    const __half* __restrict__ g16, const float* __restrict__ ssq,
    const int* __restrict__ ei, float* __restrict__ out, int E, int N)
{
    const int tid  = threadIdx.x;
    const int sub  = tid & 7;                       // lane within 8-lane group
    const int e0   = blockIdx.x * 32 + (tid >> 3);  // edge id for this group
    const int e    = min(e0, E - 1);                // clamp: keep lanes active

    int c = ei[e];
    int r = ei[E + e];
    c = min(max(c, 0), N - 1);
    r = min(max(r, 0), N - 1);

    float sc0 = 0.f, sc1 = 0.f, sr0 = 0.f, sr1 = 0.f;
    if (sub == 0) {
        sc0 = __ldg(ssq + c);
        sc1 = __ldg(ssq + NPAD + c);
        sr0 = __ldg(ssq + r);
        sr1 = __ldg(ssq + NPAD + r);
    }

    const uint4* pa = (const uint4*)(g16 + (size_t)c * H256);
    const uint4* pb = (const uint4*)(g16 + (size_t)r * H256);

    float s = 0.0f;
#pragma unroll
    for (int j = 0; j < 4; j++) {
        uint4 a = pa[sub + j * 8];
        uint4 b = pb[sub + j * 8];
        const __half2* ha = (const __half2*)&a;
        const __half2* hb = (const __half2*)&b;
        __half2 acc = __hmul2(ha[0], hb[0]);        // fp16 chain depth 4
        acc = __hfma2(ha[1], hb[1], acc);
        acc = __hfma2(ha[2], hb[2], acc);
        acc = __hfma2(ha[3], hb[3], acc);
        float2 f = __half22float2(acc);
        s += f.x + f.y;                             // fp32 across chains
    }
    s += __shfl_xor_sync(0xffffffffu, s, 1);
    s += __shfl_xor_sync(0xffffffffu, s, 2);
    s += __shfl_xor_sync(0xffffffffu, s, 4);

    if (sub == 0 && e0 < E) {
        float nc = fmaxf(sqrtf(sc0 + sc1), 1e-8f);
        float nr = fmaxf(sqrtf(sr0 + sr1), 1e-8f);
        out[e0] = s / (nc * nr);
    }
}

// ---------------------------------------------------------------------------
extern "C" void kernel_launch(void* const* d_in, const int* in_sizes, int n_in,
                              void* d_out, int out_size)
{
    const float* emb = (const float*)d_in[0];
    const int*   ei  = (const int*)d_in[1];
    const float* W1  = (const float*)d_in[2];
    const float* b1  = (const float*)d_in[3];
    const float* W2  = (const float*)d_in[4];
    const float* b2  = (const float*)d_in[5];
    float*       out = (float*)d_out;

    const int Hn = in_sizes[3];
    const int N  = in_sizes[0] / Hn;
    const int E  = in_sizes[1] / 2;
    if (Hn != H256 || N > NPAD) return;

    float* ssbuf;
    __half *g16, *h16, *w1, *w2;
    cudaGetSymbolAddress((void**)&g16,   g_g16);
    cudaGetSymbolAddress((void**)&h16,   g_h16);
    cudaGetSymbolAddress((void**)&w1,    g_w1);
    cudaGetSymbolAddress((void**)&w2,    g_w2);
    cudaGetSymbolAddress((void**)&ssbuf, g_sumsq);

    cudaFuncSetAttribute(gemm_hmma, cudaFuncAttributeMaxDynamicSharedMemorySize, SMEM_BYTES);

    prep_w<<<(H256 * H256 + 255) / 256, 256>>>(W1, W2, w1, w2);

    // Persistent: 296 CTAs (2/SM), each owns a col half + strided row tiles.
    gemm_hmma<<<2 * RT_STRIDE, 256, SMEM_BYTES>>>(emb, nullptr, w1, b1, N, 0,
                                                  h16, nullptr);
    gemm_hmma<<<2 * RT_STRIDE, 256, SMEM_BYTES>>>(nullptr, h16, w2, b2, N, 1,
                                                  g16, ssbuf);
    edge_kernel<<<(E + 31) / 32, 256>>>(g16, ssbuf, ei, out, E, N);
}